// round 1
// baseline (speedup 1.0000x reference)
#include <cuda_runtime.h>
#include <float.h>

#define N 16384
#define H 64
#define EPSF 1e-8f
#define NBLK 128
#define TPB 128
#define SORT_THREADS 1024

// ---------------- scratch (device globals; no allocation allowed) ------------
__device__ float g_sorted[N];
__device__ float g_pmse[NBLK];
__device__ float g_pd2[NBLK];
__device__ float g_pdens[NBLK];
__device__ float g_pdmax[NBLK];

// ---------------- warp reduce helpers ----------------------------------------
__device__ __forceinline__ float warp_sum(float v) {
#pragma unroll
    for (int o = 16; o > 0; o >>= 1) v += __shfl_xor_sync(0xffffffffu, v, o);
    return v;
}
__device__ __forceinline__ float warp_max(float v) {
#pragma unroll
    for (int o = 16; o > 0; o >>= 1) v = fmaxf(v, __shfl_xor_sync(0xffffffffu, v, o));
    return v;
}

// ---------------- 1) bitonic sort of x into g_sorted (single block) ----------
__global__ void sort_kernel(const float* __restrict__ x) {
    extern __shared__ float s[];
    for (int i = threadIdx.x; i < N; i += blockDim.x) s[i] = x[i];
    __syncthreads();

    for (int k = 2; k <= N; k <<= 1) {
        for (int j = k >> 1; j > 0; j >>= 1) {
#pragma unroll 4
            for (int t = threadIdx.x; t < N; t += SORT_THREADS) {
                int ixj = t ^ j;
                if (ixj > t) {
                    float a = s[t];
                    float b = s[ixj];
                    bool up = ((t & k) == 0);
                    if ((a > b) == up) { s[t] = b; s[ixj] = a; }
                }
            }
            __syncthreads();
        }
    }
    for (int i = threadIdx.x; i < N; i += blockDim.x) g_sorted[i] = s[i];
}

// ---------------- 2) MLP: mse partials + (d2y/dx2)^2 partials ----------------
__global__ void mlp_kernel(const float* __restrict__ x,
                           const float* __restrict__ tgt,
                           const float* __restrict__ w1,
                           const float* __restrict__ b1,
                           const float* __restrict__ w2,
                           const float* __restrict__ b2) {
    __shared__ float sw1[H], sb1[H], sw2[H], sc2[H];
    __shared__ float red_mse[TPB / 32], red_d2[TPB / 32];

    int tid = threadIdx.x;
    if (tid < H) {
        float a = w1[tid];
        float c = w2[tid];
        sw1[tid] = a;
        sb1[tid] = b1[tid];
        sw2[tid] = c;
        sc2[tid] = -2.0f * c * a * a;   // coefficient of t*(1-t^2) in d2y/dx2
    }
    __syncthreads();

    int i = blockIdx.x * TPB + tid;
    float xv = x[i];
    float pred = b2[0];
    float d2 = 0.0f;
#pragma unroll
    for (int h = 0; h < H; ++h) {
        float t = tanhf(fmaf(xv, sw1[h], sb1[h]));
        pred = fmaf(sw2[h], t, pred);
        float g = t * fmaf(-t, t, 1.0f);        // t - t^3
        d2 = fmaf(sc2[h], g, d2);
    }
    float e = pred - tgt[i];
    float vm = e * e;
    float vd = d2 * d2;

    vm = warp_sum(vm);
    vd = warp_sum(vd);
    if ((tid & 31) == 0) {
        red_mse[tid >> 5] = vm;
        red_d2[tid >> 5] = vd;
    }
    __syncthreads();
    if (tid < 32) {
        float m = (tid < TPB / 32) ? red_mse[tid] : 0.0f;
        float d = (tid < TPB / 32) ? red_d2[tid] : 0.0f;
        m = warp_sum(m);
        d = warp_sum(d);
        if (tid == 0) {
            g_pmse[blockIdx.x] = m;
            g_pd2[blockIdx.x] = d;
        }
    }
}

// ---------------- 3) density from sorted order -------------------------------
__global__ void density_kernel() {
    __shared__ float red_sum[TPB / 32], red_max[TPB / 32];
    int tid = threadIdx.x;
    int i = blockIdx.x * TPB + tid;

    float xi = g_sorted[i];
    float c0 = (i >= 1)     ? xi - g_sorted[i - 1] : FLT_MAX;
    float c1 = (i >= 2)     ? xi - g_sorted[i - 2] : FLT_MAX;
    float c2 = (i + 1 < N)  ? g_sorted[i + 1] - xi : FLT_MAX;
    float c3 = (i + 2 < N)  ? g_sorted[i + 2] - xi : FLT_MAX;
    // sorted => c1 >= c0, c3 >= c2. Two smallest among {c0,c1,c2,c3}:
    float m1 = fminf(c0, c2);
    float m2 = (c0 < c2) ? fminf(c1, c2) : fminf(c0, c3);

    // reference: knn vals = {EPS, m1+EPS, m2+EPS}; mean = (m1+m2+3EPS)/3
    float knn_mean = (m1 + m2 + 3.0f * EPSF) * (1.0f / 3.0f);
    float dens = 1.0f / (knn_mean + EPSF);

    float vs = warp_sum(dens);
    float vx = warp_max(dens);
    if ((tid & 31) == 0) {
        red_sum[tid >> 5] = vs;
        red_max[tid >> 5] = vx;
    }
    __syncthreads();
    if (tid < 32) {
        float s = (tid < TPB / 32) ? red_sum[tid] : 0.0f;
        float x2 = (tid < TPB / 32) ? red_max[tid] : 0.0f;
        s = warp_sum(s);
        x2 = warp_max(x2);
        if (tid == 0) {
            g_pdens[blockIdx.x] = s;
            g_pdmax[blockIdx.x] = x2;
        }
    }
}

// ---------------- 4) finalize -------------------------------------------------
__global__ void finalize_kernel(float* __restrict__ out) {
    __shared__ float r0[4], r1[4], r2[4], r3[4];
    int tid = threadIdx.x;  // 128 threads, NBLK = 128 partials

    float vm = g_pmse[tid];
    float vd = g_pd2[tid];
    float vs = g_pdens[tid];
    float vx = g_pdmax[tid];

    vm = warp_sum(vm);
    vd = warp_sum(vd);
    vs = warp_sum(vs);
    vx = warp_max(vx);
    if ((tid & 31) == 0) {
        r0[tid >> 5] = vm; r1[tid >> 5] = vd; r2[tid >> 5] = vs; r3[tid >> 5] = vx;
    }
    __syncthreads();
    if (tid == 0) {
        float mse = (r0[0] + r0[1] + r0[2] + r0[3]) * (1.0f / N);
        float md2 = (r1[0] + r1[1] + r1[2] + r1[3]) * (1.0f / N);
        float dsum = (r2[0] + r2[1] + r2[2] + r2[3]);
        float dmax = fmaxf(fmaxf(r3[0], r3[1]), fmaxf(r3[2], r3[3]));

        // density normalized: dens / (dmax + EPS); mean(weights) = 1 + 0.1*mean(dens_norm)
        float mean_dnorm = (dsum * (1.0f / N)) / (dmax + EPSF);
        float mean_w = 1.0f + 0.1f * mean_dnorm;
        float penalty = 0.01f * mean_w * md2;
        float total = mse + penalty;
        out[0] = total;
        out[1] = mse;
        out[2] = penalty;
    }
}

// ---------------- launch ------------------------------------------------------
extern "C" void kernel_launch(void* const* d_in, const int* in_sizes, int n_in,
                              void* d_out, int out_size) {
    const float* x   = (const float*)d_in[0];
    const float* tgt = (const float*)d_in[1];
    const float* w1  = (const float*)d_in[2];
    const float* b1  = (const float*)d_in[3];
    const float* w2  = (const float*)d_in[4];
    const float* b2  = (const float*)d_in[5];
    float* out = (float*)d_out;

    static bool attr_set = false;
    if (!attr_set) {
        cudaFuncSetAttribute(sort_kernel,
                             cudaFuncAttributeMaxDynamicSharedMemorySize,
                             N * (int)sizeof(float));
        attr_set = true;
    }

    sort_kernel<<<1, SORT_THREADS, N * sizeof(float)>>>(x);
    mlp_kernel<<<NBLK, TPB>>>(x, tgt, w1, b1, w2, b2);
    density_kernel<<<NBLK, TPB>>>();
    finalize_kernel<<<1, TPB>>>(out);
    (void)in_sizes; (void)n_in; (void)out_size;
}